// round 4
// baseline (speedup 1.0000x reference)
#include <cuda_runtime.h>
#include <cuda_bf16.h>
#include <float.h>
#include <math.h>

// Problem geometry (fixed by the dataset): N=32768 rows, D=768 dims,
// labels in [0,100), end_i=(task_id+1)*10=100.  Scratch sized for
// MAXC=128 classes; end_i read from device-side task_id.
#define DDIM   768
#define DV4    (DDIM / 4)      // 192 float4 per row
#define MAXC   128
#define NMAX   32768
#define CH     256
#define NBMAX  (NMAX / CH)     // 128 row chunks
#define SPLIT  8
#define RPB    4               // rows per block in the loss kernel
#define C2MAX  (2 * MAXC)      // 256 (also the stride of g_zT)

// -------- device scratch (static: no allocations allowed) --------
__device__ int    g_blockcnt[NBMAX][MAXC];
__device__ int    g_blockpre[NBMAX][MAXC];
__device__ int    g_counts[MAXC];
__device__ int    g_offsets[MAXC];
__device__ int    g_sorted[NMAX];
__device__ float4 g_part[2][SPLIT][MAXC][DV4];
__device__ float  g_z[C2MAX * DDIM];      // normalized prototypes, row major
__device__ float  g_zT[DDIM][C2MAX];      // transposed for coalesced GEMM reads
__device__ float  g_rowloss[C2MAX];

__device__ __forceinline__ int read_endi(const int* task) {
    return (task[0] + 1) * 10;
}

// ---------------- K1: per-chunk label histogram ----------------
__global__ __launch_bounds__(CH) void k_count(const int* __restrict__ labels, int N) {
    __shared__ int h[MAXC];
    int t = threadIdx.x;
    if (t < MAXC) h[t] = 0;
    __syncthreads();
    int r = blockIdx.x * CH + t;
    if (r < N) {
        int c = labels[r];
        if ((unsigned)c < MAXC) atomicAdd(&h[c], 1);
    }
    __syncthreads();
    if (t < MAXC) g_blockcnt[blockIdx.x][t] = h[t];
}

// ---------------- K2: block-prefix per class + class offsets ----------------
__global__ __launch_bounds__(MAXC) void k_scan(const int* __restrict__ task, int NB) {
    __shared__ int s_cnt[MAXC];
    int c = threadIdx.x;
    int run = 0;
    for (int b = 0; b < NB; b++) {
        g_blockpre[b][c] = run;
        run += g_blockcnt[b][c];
    }
    g_counts[c] = run;
    s_cnt[c] = run;
    __syncthreads();
    if (c == 0) {
        int end_i = read_endi(task);
        if (end_i > MAXC) end_i = MAXC;
        int acc = 0;
        for (int cc = 0; cc < end_i; cc++) { g_offsets[cc] = acc; acc += s_cnt[cc]; }
    }
}

// ---------------- K3: stable scatter (deterministic counting sort) ----------------
__global__ __launch_bounds__(CH) void k_scatter(const int* __restrict__ labels,
                                                const int* __restrict__ task, int N) {
    __shared__ int sl[CH];
    int t = threadIdx.x;
    int r = blockIdx.x * CH + t;
    sl[t] = (r < N) ? labels[r] : -1;
    __syncthreads();
    int end_i = read_endi(task);
    if (r < N) {
        int c = sl[t];
        if (c >= 0 && c < end_i && c < MAXC) {
            int rank = 0;
            for (int j = 0; j < t; j++) rank += (sl[j] == c);   // uniform j -> LDS broadcast
            g_sorted[g_offsets[c] + g_blockpre[blockIdx.x][c] + rank] = r;
        }
    }
}

// ---------------- K4: segment sums (the HBM-bound kernel) ----------------
__global__ __launch_bounds__(192) void k_segsum(const float* __restrict__ z1,
                                                const float* __restrict__ z2,
                                                const int* __restrict__ task) {
    int end_i = read_endi(task);
    int bid = blockIdx.x;                 // [0, MAXC*2*SPLIT)
    int c   = bid / (2 * SPLIT);
    int rem = bid % (2 * SPLIT);
    int tn  = rem / SPLIT;                // which tensor
    int s   = rem % SPLIT;                // row split
    if (c >= end_i || c >= MAXC) return;

    const float4* __restrict__ z = (const float4*)(tn ? z2 : z1);
    int cnt = g_counts[c];
    int off = g_offsets[c];
    int r0  = (int)((long long)cnt * s / SPLIT);
    int r1  = (int)((long long)cnt * (s + 1) / SPLIT);
    int t   = threadIdx.x;
    int n   = r1 - r0;
    const int* __restrict__ srt = g_sorted + off + r0;

    // Unroll x2: two independent LDG.128 chains in flight per thread (MLP=2).
    float4 acc0 = make_float4(0.f, 0.f, 0.f, 0.f);
    float4 acc1 = make_float4(0.f, 0.f, 0.f, 0.f);
    int r = 0;
    for (; r + 2 <= n; r += 2) {
        size_t i0 = (size_t)srt[r]     * DV4 + t;
        size_t i1 = (size_t)srt[r + 1] * DV4 + t;
        float4 v0 = __ldcs(z + i0);     // streaming: read-once, evict-first
        float4 v1 = __ldcs(z + i1);
        acc0.x += v0.x; acc0.y += v0.y; acc0.z += v0.z; acc0.w += v0.w;
        acc1.x += v1.x; acc1.y += v1.y; acc1.z += v1.z; acc1.w += v1.w;
    }
    if (r < n) {
        float4 v0 = __ldcs(z + (size_t)srt[r] * DV4 + t);
        acc0.x += v0.x; acc0.y += v0.y; acc0.z += v0.z; acc0.w += v0.w;
    }
    acc0.x += acc1.x; acc0.y += acc1.y; acc0.z += acc1.z; acc0.w += acc1.w;
    g_part[tn][s][c][t] = acc0;
}

// ---------------- K5: reduce splits, write prototypes, normalize ----------------
__global__ __launch_bounds__(192) void k_finalize(const int* __restrict__ task,
                                                  float* __restrict__ out) {
    int end_i = read_endi(task);
    int C2 = 2 * end_i;
    int i = blockIdx.x;
    if (i >= C2) return;
    int tn = (i < end_i) ? 0 : 1;
    int c  = i - tn * end_i;
    int t  = threadIdx.x;

    float4 s4 = make_float4(0.f, 0.f, 0.f, 0.f);
    #pragma unroll
    for (int s = 0; s < SPLIT; s++) {       // fixed order -> deterministic
        float4 v = g_part[tn][s][c][t];
        s4.x += v.x; s4.y += v.y; s4.z += v.z; s4.w += v.w;
    }
    float denom = fmaxf((float)g_counts[c], 1.0f);
    float4 p4 = make_float4(s4.x / denom, s4.y / denom, s4.z / denom, s4.w / denom);

    // prototypes (unnormalized) into d_out; out+1 is only 4B aligned -> scalar stores
    float* po = out + 1 + (size_t)(tn * end_i + c) * DDIM + t * 4;
    po[0] = p4.x; po[1] = p4.y; po[2] = p4.z; po[3] = p4.w;

    // BUGFIX (R3): 192-entry tree reduction with o=96..1 drops red[2] after the
    // o=3 step (192 = 2^6 * 3).  Pad to 256 and reduce with a clean power-of-2
    // tree instead.
    __shared__ float red[256];
    red[t] = p4.x * p4.x + p4.y * p4.y + p4.z * p4.z + p4.w * p4.w;
    if (t < 64) red[t + 192] = 0.0f;
    __syncthreads();
    for (int o = 128; o > 0; o >>= 1) {
        if (t < o) red[t] += red[t + o];
        __syncthreads();
    }
    float nrm = fmaxf(sqrtf(red[0]), 1e-12f);
    float inv = 1.0f / nrm;
    float4 q4 = make_float4(p4.x * inv, p4.y * inv, p4.z * inv, p4.w * inv);

    ((float4*)(g_z + (size_t)i * DDIM))[t] = q4;
    g_zT[t * 4 + 0][i] = q4.x;
    g_zT[t * 4 + 1][i] = q4.y;
    g_zT[t * 4 + 2][i] = q4.z;
    g_zT[t * 4 + 3][i] = q4.w;
}

// ---------------- K6: fused logits + per-row log-softmax positive term ----------------
__global__ __launch_bounds__(256) void k_logits(const int* __restrict__ task) {
    int end_i = read_endi(task);
    int C2 = 2 * end_i;
    int i0 = blockIdx.x * RPB;
    if (i0 >= C2) return;
    int t = threadIdx.x;
    int nrows = min(RPB, C2 - i0);

    __shared__ float s_zi[RPB][DDIM];
    __shared__ float s_red[256];
    __shared__ float s_pl;      // (logit - rowmax) at the partner column
    __shared__ int   s_pv;      // partner validity

    if (t < DV4) {
        for (int rr = 0; rr < nrows; rr++) {
            ((float4*)s_zi[rr])[t] = ((const float4*)(g_z + (size_t)(i0 + rr) * DDIM))[t];
        }
    }
    __syncthreads();

    int  j   = t;
    bool jin = (j < C2);
    bool vj  = false;
    if (jin) {
        int cj = (j < end_i) ? j : j - end_i;
        vj = (g_counts[cj] > 0);
    }

    float dot[RPB] = {0.f, 0.f, 0.f, 0.f};
    if (jin) {
        #pragma unroll 4
        for (int k = 0; k < DDIM; k++) {
            float b = g_zT[k][j];           // coalesced across threads
            #pragma unroll
            for (int rr = 0; rr < RPB; rr++) dot[rr] += s_zi[rr][k] * b;
        }
    }

    for (int rr = 0; rr < nrows; rr++) {
        int i  = i0 + rr;
        int pi = (i < end_i) ? i + end_i : i - end_i;   // the single positive
        float l  = dot[rr] * 2.0f;                      // 1 / TEMPERATURE
        float lv = (jin && vj) ? l : -FLT_MAX;

        // row max over valid columns (diagonal included, per reference)
        s_red[t] = lv;
        __syncthreads();
        for (int o = 128; o > 0; o >>= 1) {
            if (t < o) s_red[t] = fmaxf(s_red[t], s_red[t + o]);
            __syncthreads();
        }
        float rowmax = s_red[0];
        __syncthreads();

        // exp-sum over valid, non-diagonal columns
        float e = (jin && vj && j != i) ? expf(l - rowmax) : 0.0f;
        s_red[t] = e;
        __syncthreads();
        for (int o = 128; o > 0; o >>= 1) {
            if (t < o) s_red[t] += s_red[t + o];
            __syncthreads();
        }
        float esum = s_red[0];
        __syncthreads();

        if (jin && j == pi) { s_pl = l - rowmax; s_pv = vj ? 1 : 0; }
        __syncthreads();

        if (t == 0) {
            int ci  = (i < end_i) ? i : i - end_i;
            bool vi = (g_counts[ci] > 0);
            float lp = s_pl - logf(esum);
            g_rowloss[i] = (vi && s_pv) ? -lp : 0.0f;
        }
        __syncthreads();
    }
}

// ---------------- K7: final deterministic reduction of the loss ----------------
__global__ __launch_bounds__(256) void k_loss(const int* __restrict__ task,
                                              float* __restrict__ out) {
    int end_i = read_endi(task);
    int C2 = 2 * end_i;
    __shared__ float red[256];
    __shared__ int   redi[256];
    int t = threadIdx.x;
    red[t]  = (t < C2) ? g_rowloss[t] : 0.0f;
    redi[t] = (t < end_i) ? ((g_counts[t] > 0) ? 2 : 0) : 0;
    __syncthreads();
    for (int o = 128; o > 0; o >>= 1) {
        if (t < o) { red[t] += red[t + o]; redi[t] += redi[t + o]; }
        __syncthreads();
    }
    if (t == 0) out[0] = red[0] / fmaxf((float)redi[0], 1.0f);
}

// ---------------- launch ----------------
extern "C" void kernel_launch(void* const* d_in, const int* in_sizes, int n_in,
                              void* d_out, int out_size) {
    const float* z1     = (const float*)d_in[0];
    const float* z2     = (const float*)d_in[1];
    const int*   labels = (const int*)d_in[2];
    const int*   task   = (const int*)d_in[3];
    float* out = (float*)d_out;

    int N  = in_sizes[2];                 // 32768
    int NB = (N + CH - 1) / CH;           // 128

    k_count  <<<NB, CH>>>(labels, N);
    k_scan   <<<1, MAXC>>>(task, NB);
    k_scatter<<<NB, CH>>>(labels, task, N);
    k_segsum <<<MAXC * 2 * SPLIT, 192>>>(z1, z2, task);
    k_finalize<<<2 * MAXC, 192>>>(task, out);
    k_logits <<<(C2MAX + RPB - 1) / RPB, 256>>>(task);
    k_loss   <<<1, 256>>>(task, out);
}

// round 12
// speedup vs baseline: 1.6321x; 1.6321x over previous
#include <cuda_runtime.h>
#include <cuda_bf16.h>
#include <float.h>
#include <math.h>

// Problem geometry (fixed by the dataset): N=32768 rows, D=768 dims,
// labels in [0,100), end_i=(task_id+1)*10=100.  Scratch sized for
// MAXC=128 classes; end_i read from device-side task_id.
#define DDIM   768
#define DV4    (DDIM / 4)      // 192 float4 per row
#define MAXC   128
#define NMAX   32768
#define CH     256
#define NBMAX  (NMAX / CH)     // 128 row chunks
#define SPLIT  8
#define RPB    2               // rows per block in the loss kernel
#define C2MAX  (2 * MAXC)      // 256 (also the stride of g_zT4)

// -------- device scratch (static: no allocations allowed) --------
__device__ int    g_blockcnt[NBMAX][MAXC];
__device__ int    g_blockpre[NBMAX][MAXC];
__device__ int    g_counts[MAXC];
__device__ int    g_offsets[MAXC];
__device__ int    g_sorted[NMAX];
__device__ float4 g_part[2][SPLIT][MAXC][DV4];
__device__ float  g_z[C2MAX * DDIM];       // normalized prototypes, row major
__device__ float4 g_zT4[DV4][C2MAX];       // k-packed transpose: [k4][j] = dims 4k4..4k4+3 of row j
__device__ float  g_rowloss[C2MAX];

__device__ __forceinline__ int read_endi(const int* task) {
    return (task[0] + 1) * 10;
}

// ---------------- K1: per-chunk label histogram ----------------
__global__ __launch_bounds__(CH) void k_count(const int* __restrict__ labels, int N) {
    __shared__ int h[MAXC];
    int t = threadIdx.x;
    if (t < MAXC) h[t] = 0;
    __syncthreads();
    int r = blockIdx.x * CH + t;
    if (r < N) {
        int c = labels[r];
        if ((unsigned)c < MAXC) atomicAdd(&h[c], 1);
    }
    __syncthreads();
    if (t < MAXC) g_blockcnt[blockIdx.x][t] = h[t];
}

// ---------------- K2: block-prefix per class + class offsets ----------------
// Batched loads (8 independent LDGs in flight) before the serial accumulate.
__global__ __launch_bounds__(MAXC) void k_scan(const int* __restrict__ task, int NB) {
    __shared__ int s_cnt[MAXC];
    int c = threadIdx.x;
    int run = 0;
    int b0 = 0;
    for (; b0 + 8 <= NB; b0 += 8) {
        int v[8];
        #pragma unroll
        for (int u = 0; u < 8; u++) v[u] = g_blockcnt[b0 + u][c];
        #pragma unroll
        for (int u = 0; u < 8; u++) { g_blockpre[b0 + u][c] = run; run += v[u]; }
    }
    for (; b0 < NB; b0++) { g_blockpre[b0][c] = run; run += g_blockcnt[b0][c]; }
    g_counts[c] = run;
    s_cnt[c] = run;
    __syncthreads();
    if (c == 0) {
        int end_i = read_endi(task);
        if (end_i > MAXC) end_i = MAXC;
        int acc = 0;
        for (int cc = 0; cc < end_i; cc++) { g_offsets[cc] = acc; acc += s_cnt[cc]; }
    }
}

// ---------------- K3: stable scatter (deterministic counting sort) ----------------
__global__ __launch_bounds__(CH) void k_scatter(const int* __restrict__ labels,
                                                const int* __restrict__ task, int N) {
    __shared__ int sl[CH];
    int t = threadIdx.x;
    int r = blockIdx.x * CH + t;
    sl[t] = (r < N) ? labels[r] : -1;
    __syncthreads();
    int end_i = read_endi(task);
    if (r < N) {
        int c = sl[t];
        if (c >= 0 && c < end_i && c < MAXC) {
            int rank = 0;
            for (int j = 0; j < t; j++) rank += (sl[j] == c);   // uniform j -> LDS broadcast
            g_sorted[g_offsets[c] + g_blockpre[blockIdx.x][c] + rank] = r;
        }
    }
}

// ---------------- K4: segment sums (the HBM-bound kernel) ----------------
// Indices staged in shared (removes the dependent L2 hit from the gather
// critical path); unroll x4 with independent accumulators (MLP=4/thread).
__global__ __launch_bounds__(192) void k_segsum(const float* __restrict__ z1,
                                                const float* __restrict__ z2,
                                                const int* __restrict__ task) {
    int end_i = read_endi(task);
    int bid = blockIdx.x;                 // [0, MAXC*2*SPLIT)
    int c   = bid / (2 * SPLIT);
    int rem = bid % (2 * SPLIT);
    int tn  = rem / SPLIT;                // which tensor
    int s   = rem % SPLIT;                // row split
    if (c >= end_i || c >= MAXC) return;

    const float4* __restrict__ z = (const float4*)(tn ? z2 : z1);
    int cnt = g_counts[c];
    int off = g_offsets[c];
    int r0  = (int)((long long)cnt * s / SPLIT);
    int r1  = (int)((long long)cnt * (s + 1) / SPLIT);
    int t   = threadIdx.x;

    __shared__ int s_idx[192];
    float4 a0 = make_float4(0.f, 0.f, 0.f, 0.f);
    float4 a1 = make_float4(0.f, 0.f, 0.f, 0.f);
    float4 a2 = make_float4(0.f, 0.f, 0.f, 0.f);
    float4 a3 = make_float4(0.f, 0.f, 0.f, 0.f);

    for (int base = r0; base < r1; base += 192) {
        int m = min(192, r1 - base);
        __syncthreads();
        if (t < m) s_idx[t] = g_sorted[off + base + t];
        __syncthreads();
        int r = 0;
        for (; r + 4 <= m; r += 4) {
            float4 v0 = __ldcs(z + (size_t)s_idx[r]     * DV4 + t);
            float4 v1 = __ldcs(z + (size_t)s_idx[r + 1] * DV4 + t);
            float4 v2 = __ldcs(z + (size_t)s_idx[r + 2] * DV4 + t);
            float4 v3 = __ldcs(z + (size_t)s_idx[r + 3] * DV4 + t);
            a0.x += v0.x; a0.y += v0.y; a0.z += v0.z; a0.w += v0.w;
            a1.x += v1.x; a1.y += v1.y; a1.z += v1.z; a1.w += v1.w;
            a2.x += v2.x; a2.y += v2.y; a2.z += v2.z; a2.w += v2.w;
            a3.x += v3.x; a3.y += v3.y; a3.z += v3.z; a3.w += v3.w;
        }
        for (; r < m; r++) {
            float4 v0 = __ldcs(z + (size_t)s_idx[r] * DV4 + t);
            a0.x += v0.x; a0.y += v0.y; a0.z += v0.z; a0.w += v0.w;
        }
    }
    // fixed combine order -> deterministic across replays
    a0.x += a1.x; a0.y += a1.y; a0.z += a1.z; a0.w += a1.w;
    a2.x += a3.x; a2.y += a3.y; a2.z += a3.z; a2.w += a3.w;
    a0.x += a2.x; a0.y += a2.y; a0.z += a2.z; a0.w += a2.w;
    g_part[tn][s][c][t] = a0;
}

// ---------------- K5: reduce splits, write prototypes, normalize ----------------
__global__ __launch_bounds__(192) void k_finalize(const int* __restrict__ task,
                                                  float* __restrict__ out) {
    int end_i = read_endi(task);
    int C2 = 2 * end_i;
    int i = blockIdx.x;
    if (i >= C2) return;
    int tn = (i < end_i) ? 0 : 1;
    int c  = i - tn * end_i;
    int t  = threadIdx.x;

    float4 s4 = make_float4(0.f, 0.f, 0.f, 0.f);
    #pragma unroll
    for (int s = 0; s < SPLIT; s++) {       // fixed order -> deterministic
        float4 v = g_part[tn][s][c][t];
        s4.x += v.x; s4.y += v.y; s4.z += v.z; s4.w += v.w;
    }
    float denom = fmaxf((float)g_counts[c], 1.0f);
    float4 p4 = make_float4(s4.x / denom, s4.y / denom, s4.z / denom, s4.w / denom);

    // prototypes (unnormalized) into d_out; out+1 is only 4B aligned -> scalar stores
    float* po = out + 1 + (size_t)(tn * end_i + c) * DDIM + t * 4;
    po[0] = p4.x; po[1] = p4.y; po[2] = p4.z; po[3] = p4.w;

    // 192 threads: pad reduction array to 256 (power-of-2 tree; see R3 bug)
    __shared__ float red[256];
    red[t] = p4.x * p4.x + p4.y * p4.y + p4.z * p4.z + p4.w * p4.w;
    if (t < 64) red[t + 192] = 0.0f;
    __syncthreads();
    for (int o = 128; o > 0; o >>= 1) {
        if (t < o) red[t] += red[t + o];
        __syncthreads();
    }
    float nrm = fmaxf(sqrtf(red[0]), 1e-12f);
    float inv = 1.0f / nrm;
    float4 q4 = make_float4(p4.x * inv, p4.y * inv, p4.z * inv, p4.w * inv);

    ((float4*)(g_z + (size_t)i * DDIM))[t] = q4;
    g_zT4[t][i] = q4;                       // single STG.128 per thread
}

// ---------------- K6: fused logits + per-row log-softmax positive term ----------------
__global__ __launch_bounds__(256) void k_logits(const int* __restrict__ task) {
    int end_i = read_endi(task);
    int C2 = 2 * end_i;
    int i0 = blockIdx.x * RPB;
    if (i0 >= C2) return;
    int t = threadIdx.x;
    int nrows = min(RPB, C2 - i0);

    __shared__ float4 s_zi4[RPB][DV4];
    __shared__ float  s_red[256];
    __shared__ float  s_pl;     // (logit - rowmax) at the partner column
    __shared__ int    s_pv;     // partner validity

    if (t < DV4) {
        for (int rr = 0; rr < nrows; rr++) {
            s_zi4[rr][t] = ((const float4*)(g_z + (size_t)(i0 + rr) * DDIM))[t];
        }
    }
    __syncthreads();

    int  j   = t;
    bool jin = (j < C2);
    bool vj  = false;
    if (jin) {
        int cj = (j < end_i) ? j : j - end_i;
        vj = (g_counts[cj] > 0);
    }

    float dot[RPB] = {0.f, 0.f};
    if (jin) {
        #pragma unroll 8
        for (int k4 = 0; k4 < DV4; k4++) {
            float4 b = g_zT4[k4][j];        // LDG.128, coalesced across j
            #pragma unroll
            for (int rr = 0; rr < RPB; rr++) {
                float4 a = s_zi4[rr][k4];   // LDS.128 broadcast
                dot[rr] += a.x * b.x + a.y * b.y + a.z * b.z + a.w * b.w;
            }
        }
    }

    for (int rr = 0; rr < nrows; rr++) {
        int i  = i0 + rr;
        int pi = (i < end_i) ? i + end_i : i - end_i;   // the single positive
        float l  = dot[rr] * 2.0f;                      // 1 / TEMPERATURE
        float lv = (jin && vj) ? l : -FLT_MAX;

        // row max over valid columns (diagonal included, per reference)
        s_red[t] = lv;
        __syncthreads();
        for (int o = 128; o > 0; o >>= 1) {
            if (t < o) s_red[t] = fmaxf(s_red[t], s_red[t + o]);
            __syncthreads();
        }
        float rowmax = s_red[0];
        __syncthreads();

        // exp-sum over valid, non-diagonal columns
        float e = (jin && vj && j != i) ? expf(l - rowmax) : 0.0f;
        s_red[t] = e;
        __syncthreads();
        for (int o = 128; o > 0; o >>= 1) {
            if (t < o) s_red[t] += s_red[t + o];
            __syncthreads();
        }
        float esum = s_red[0];
        __syncthreads();

        if (jin && j == pi) { s_pl = l - rowmax; s_pv = vj ? 1 : 0; }
        __syncthreads();

        if (t == 0) {
            int ci  = (i < end_i) ? i : i - end_i;
            bool vi = (g_counts[ci] > 0);
            float lp = s_pl - logf(esum);
            g_rowloss[i] = (vi && s_pv) ? -lp : 0.0f;
        }
        __syncthreads();
    }
}

// ---------------- K7: final deterministic reduction of the loss ----------------
__global__ __launch_bounds__(256) void k_loss(const int* __restrict__ task,
                                              float* __restrict__ out) {
    int end_i = read_endi(task);
    int C2 = 2 * end_i;
    __shared__ float red[256];
    __shared__ int   redi[256];
    int t = threadIdx.x;
    red[t]  = (t < C2) ? g_rowloss[t] : 0.0f;
    redi[t] = (t < end_i) ? ((g_counts[t] > 0) ? 2 : 0) : 0;
    __syncthreads();
    for (int o = 128; o > 0; o >>= 1) {
        if (t < o) { red[t] += red[t + o]; redi[t] += redi[t + o]; }
        __syncthreads();
    }
    if (t == 0) out[0] = red[0] / fmaxf((float)redi[0], 1.0f);
}

// ---------------- launch ----------------
extern "C" void kernel_launch(void* const* d_in, const int* in_sizes, int n_in,
                              void* d_out, int out_size) {
    const float* z1     = (const float*)d_in[0];
    const float* z2     = (const float*)d_in[1];
    const int*   labels = (const int*)d_in[2];
    const int*   task   = (const int*)d_in[3];
    float* out = (float*)d_out;

    int N  = in_sizes[2];                 // 32768
    int NB = (N + CH - 1) / CH;           // 128

    k_count  <<<NB, CH>>>(labels, N);
    k_scan   <<<1, MAXC>>>(task, NB);
    k_scatter<<<NB, CH>>>(labels, task, N);
    k_segsum <<<MAXC * 2 * SPLIT, 192>>>(z1, z2, task);
    k_finalize<<<2 * MAXC, 192>>>(task, out);
    k_logits <<<C2MAX / RPB, 256>>>(task);
    k_loss   <<<1, 256>>>(task, out);
}